// round 1
// baseline (speedup 1.0000x reference)
#include <cuda_runtime.h>
#include <math.h>

// ---------------- problem constants ----------------
#define BATCH 32
#define SEQL  128
#define EMB   768
#define HID   512
#define FH    2048          // 4*HID
#define NPTS  1024
#define PDIM  256
#define NHEAD 4
#define HDIM  128
#define NBLK  5
#define NSEG  4
#define ROWS  (BATCH*SEQL)  // 4096
#define SCALE_ATT 0.08838834764831845f  // 1/sqrt(128)

// ---------------- scratch (device globals; no allocation allowed) ----------------
__device__ float d_mid  [NBLK * ROWS * HID];      // MLP intermediate
__device__ float d_hmlp [NBLK * ROWS * HID];      // MLP output (LSTM input)
__device__ float d_G    [NBLK * ROWS * FH];       // precomputed input projections (reused per layer)
__device__ float d_h0seq[NBLK * ROWS * HID];      // layer0 hidden sequence
__device__ float d_h1seq[NBLK * ROWS * HID];      // layer1 hidden sequence
__device__ float d_hst  [2 * NBLK * BATCH * HID]; // double-buffered h state
__device__ float d_cst  [NBLK * BATCH * HID];     // c state
__device__ float d_bout [NBLK * BATCH * HID];     // blk_out
__device__ float d_kbuf [NSEG * BATCH * NPTS * HID];
__device__ float d_vbuf [NSEG * BATCH * NPTS * HID];
__device__ float d_qbuf [NSEG * BATCH * HID];
__device__ float d_abuf [NSEG * BATCH * HID];     // attention output (pre-Wo)

// ---------------- generic tiled SGEMM: C = act(A@W + b1 + b2) ----------------
// A: MxK row-major, W: KxN row-major. M%64==0, N%64==0, K%16==0. batch via z.
__global__ void k_gemm(const float* __restrict__ A, const float* __restrict__ W,
                       const float* __restrict__ b1, const float* __restrict__ b2,
                       float* __restrict__ C,
                       int M, int N, int K,
                       long sA, long sW, long sB, long sC, int act)
{
    int z = blockIdx.z;
    A += z * sA; W += z * sW; C += z * sC;
    const float* bias1 = b1 ? b1 + z * sB : nullptr;
    const float* bias2 = b2 ? b2 + z * sB : nullptr;

    __shared__ float As[16][64];
    __shared__ float Ws[16][64];

    int tid = threadIdx.x;
    int tx = tid % 16, ty = tid / 16;
    int m0 = blockIdx.y * 64, n0 = blockIdx.x * 64;

    int a_row = tid >> 2;            // 0..63
    int a_kv  = (tid & 3) * 4;       // 0,4,8,12
    int w_kk  = tid >> 4;            // 0..15
    int w_nv  = (tid & 15) * 4;      // 0..60

    float acc[4][4] = {};

    for (int k0 = 0; k0 < K; k0 += 16) {
        float4 av = *(const float4*)(A + (long)(m0 + a_row) * K + k0 + a_kv);
        As[a_kv + 0][a_row] = av.x;
        As[a_kv + 1][a_row] = av.y;
        As[a_kv + 2][a_row] = av.z;
        As[a_kv + 3][a_row] = av.w;
        *(float4*)&Ws[w_kk][w_nv] = *(const float4*)(W + (long)(k0 + w_kk) * N + n0 + w_nv);
        __syncthreads();
        #pragma unroll
        for (int k = 0; k < 16; k++) {
            float4 a4 = *(const float4*)&As[k][ty * 4];
            float4 b4 = *(const float4*)&Ws[k][tx * 4];
            float ar[4] = {a4.x, a4.y, a4.z, a4.w};
            float br[4] = {b4.x, b4.y, b4.z, b4.w};
            #pragma unroll
            for (int i = 0; i < 4; i++)
                #pragma unroll
                for (int j = 0; j < 4; j++)
                    acc[i][j] += ar[i] * br[j];
        }
        __syncthreads();
    }

    #pragma unroll
    for (int i = 0; i < 4; i++) {
        int m = m0 + ty * 4 + i;
        #pragma unroll
        for (int j = 0; j < 4; j++) {
            int n = n0 + tx * 4 + j;
            float v = acc[i][j];
            if (bias1) v += bias1[n];
            if (bias2) v += bias2[n];
            if (act == 1) v = (v > 0.f) ? v : 0.01f * v;   // leaky_relu(0.01)
            C[(long)m * N + n] = v;
        }
    }
}

__global__ void k_zero(float* p, int n)
{
    int i = blockIdx.x * blockDim.x + threadIdx.x;
    if (i < n) p[i] = 0.f;
}

// ---------------- fused LSTM step: gpre = G[t] + h@Whh, then gates ----------------
// grid (32, 5): blockIdx.x selects 16-wide m-chunk (covers all 4 gates for those m),
// blockIdx.y = block index i. 256 threads. Double-buffered h (hin/hout).
__global__ void k_step(const float* __restrict__ Whh,   // already layer-offset base
                       const float* __restrict__ G,
                       const float* __restrict__ hin, float* __restrict__ hout,
                       float* __restrict__ cst, float* __restrict__ hseq, int t)
{
    int i  = blockIdx.y;
    int c0 = blockIdx.x * 16;
    const float* Wi   = Whh + (long)i * 2 * HID * FH;
    const float* hrow = hin + (long)i * BATCH * HID;

    __shared__ float hsh[32][16];
    __shared__ float Wsh[16][64];
    __shared__ float gsh[32][64];

    int tid = threadIdx.x;
    int tx = tid % 16;       // 4 cols each
    int ty = tid / 16;       // 2 rows each

    int kk   = tid >> 4;          // 0..15
    int jgrp = tid & 15;          // float4 col group
    int gate = jgrp >> 2;
    int ncol4 = gate * HID + c0 + (jgrp & 3) * 4;

    float acc[2][4] = {};

    for (int k0 = 0; k0 < HID; k0 += 16) {
        int l = tid;
        hsh[l >> 4][l & 15] = hrow[(l >> 4) * HID + k0 + (l & 15)];
        l = tid + 256;
        hsh[l >> 4][l & 15] = hrow[(l >> 4) * HID + k0 + (l & 15)];
        *(float4*)&Wsh[kk][jgrp * 4] = *(const float4*)(Wi + (long)(k0 + kk) * FH + ncol4);
        __syncthreads();
        #pragma unroll
        for (int k = 0; k < 16; k++) {
            float4 w4 = *(const float4*)&Wsh[k][tx * 4];
            float ha = hsh[ty * 2][k];
            float hb = hsh[ty * 2 + 1][k];
            acc[0][0] += ha * w4.x; acc[0][1] += ha * w4.y;
            acc[0][2] += ha * w4.z; acc[0][3] += ha * w4.w;
            acc[1][0] += hb * w4.x; acc[1][1] += hb * w4.y;
            acc[1][2] += hb * w4.z; acc[1][3] += hb * w4.w;
        }
        __syncthreads();
    }

    // add precomputed input projection, stage for gate exchange
    int nb = (tx >> 2) * HID + c0 + (tx & 3) * 4;  // matches cols tx*4..tx*4+3
    #pragma unroll
    for (int r = 0; r < 2; r++) {
        int b = ty * 2 + r;
        float4 g4 = *(const float4*)(G + (((long)i * BATCH + b) * SEQL + t) * FH + nb);
        float4 o;
        o.x = acc[r][0] + g4.x; o.y = acc[r][1] + g4.y;
        o.z = acc[r][2] + g4.z; o.w = acc[r][3] + g4.w;
        *(float4*)&gsh[b][tx * 4] = o;
    }
    __syncthreads();

    // gate math: gsh[b][gate*16 + ml] == pre-activation for n = gate*512 + c0 + ml
    for (int s = tid; s < 512; s += 256) {
        int b  = s >> 4;
        int ml = s & 15;
        float ipre = gsh[b][ 0 + ml];
        float fpre = gsh[b][16 + ml];
        float gpre = gsh[b][32 + ml];
        float opre = gsh[b][48 + ml];
        int m = c0 + ml;
        long ci = (long)i * BATCH * HID + (long)b * HID + m;
        float cold = cst[ci];
        float ig = 1.f / (1.f + expf(-ipre));
        float fg = 1.f / (1.f + expf(-fpre));
        float og = 1.f / (1.f + expf(-opre));
        float cn = fg * cold + ig * tanhf(gpre);
        float hn = og * tanhf(cn);
        cst[ci]  = cn;
        hout[ci] = hn;
        hseq[(((long)i * BATCH + b) * SEQL + t) * HID + m] = hn;
    }
}

// ---------------- gather last timestep + linear ----------------
__global__ void k_blkout(const float* __restrict__ h1seq, const int* __restrict__ text_length,
                         const float* __restrict__ linW, const float* __restrict__ linb,
                         float* __restrict__ bout)
{
    int i = blockIdx.x, b = blockIdx.y, tid = threadIdx.x;
    int len = text_length[b * NBLK + i];
    const float* last = h1seq + (((long)i * BATCH + b) * SEQL + (len - 1)) * HID;
    __shared__ float lsh[HID];
    lsh[tid] = last[tid];
    lsh[tid + 256] = last[tid + 256];
    __syncthreads();
    const float* W = linW + (long)i * HID * HID;
    for (int n = tid; n < HID; n += 256) {
        float s = linb[i * HID + n];
        #pragma unroll 4
        for (int k = 0; k < HID; k++) s += lsh[k] * W[(long)k * HID + n];
        bout[((long)i * BATCH + b) * HID + n] = s;
    }
}

// ---------------- q projection ----------------
__global__ void k_qproj(const float* __restrict__ bout, const float* __restrict__ Wq,
                        const float* __restrict__ bq, float* __restrict__ q)
{
    int s = blockIdx.x, b = blockIdx.y, tid = threadIdx.x;
    __shared__ float z[HID];
    const float* zin = bout + (((long)(s + 1) * BATCH) + b) * HID;
    z[tid] = zin[tid];
    z[tid + 256] = zin[tid + 256];
    __syncthreads();
    const float* W = Wq + (long)s * HID * HID;
    for (int n = tid; n < HID; n += 256) {
        float acc = bq[s * HID + n];
        #pragma unroll 4
        for (int k = 0; k < HID; k++) acc += z[k] * W[(long)k * HID + n];
        q[((long)s * BATCH + b) * HID + n] = acc;
    }
}

// ---------------- masked attention per (head, batch, seg) ----------------
__global__ void k_attn(const float* __restrict__ q, const float* __restrict__ kbuf,
                       const float* __restrict__ vbuf, const int* __restrict__ pmask,
                       float* __restrict__ aout)
{
    int h = blockIdx.x, b = blockIdx.y, s = blockIdx.z;
    int tid = threadIdx.x;
    __shared__ float qsh[HDIM];
    __shared__ float sc[NPTS];
    __shared__ float red[256];

    long rowbase = ((long)s * BATCH + b) * NPTS;
    const float* qrow = q + ((long)s * BATCH + b) * HID + h * HDIM;
    if (tid < HDIM) qsh[tid] = qrow[tid];
    __syncthreads();

    float lmax = -1e30f;
    for (int n = tid; n < NPTS; n += 256) {
        const float* kr = kbuf + (rowbase + n) * HID + h * HDIM;
        float d = 0.f;
        #pragma unroll
        for (int c = 0; c < HDIM; c += 4) {
            float4 k4 = *(const float4*)(kr + c);
            float4 q4 = *(const float4*)(qsh + c);
            d += k4.x * q4.x + k4.y * q4.y + k4.z * q4.z + k4.w * q4.w;
        }
        float v = (pmask[b * NPTS + n] == s + 1) ? d * SCALE_ATT : -1e9f;
        sc[n] = v;
        lmax = fmaxf(lmax, v);
    }
    red[tid] = lmax; __syncthreads();
    for (int off = 128; off > 0; off >>= 1) {
        if (tid < off) red[tid] = fmaxf(red[tid], red[tid + off]);
        __syncthreads();
    }
    float mx = red[0];
    __syncthreads();

    float lsum = 0.f;
    for (int n = tid; n < NPTS; n += 256) {
        float e = expf(sc[n] - mx);
        sc[n] = e;
        lsum += e;
    }
    red[tid] = lsum; __syncthreads();
    for (int off = 128; off > 0; off >>= 1) {
        if (tid < off) red[tid] += red[tid + off];
        __syncthreads();
    }
    float inv = 1.f / red[0];
    __syncthreads();

    int d = tid & 127, half = tid >> 7;
    const float* vb = vbuf + rowbase * HID + h * HDIM + d;
    float acc = 0.f;
    int nbeg = half * 512;
    #pragma unroll 4
    for (int n = nbeg; n < nbeg + 512; n++) acc += sc[n] * vb[(long)n * HID];
    red[tid] = acc; __syncthreads();
    if (tid < HDIM)
        aout[((long)s * BATCH + b) * HID + h * HDIM + tid] = (red[tid] + red[tid + 128]) * inv;
}

// ---------------- seg output: segs + where(any, attn@Wo + bo, 0) -> d_out ----------------
__global__ void k_segfinal(const float* __restrict__ abuf, const float* __restrict__ Wo,
                           const float* __restrict__ bo, const float* __restrict__ bout,
                           const int* __restrict__ pmask, float* __restrict__ out)
{
    int s = blockIdx.x, b = blockIdx.y, tid = threadIdx.x;
    __shared__ float ash[HID];
    __shared__ int anyf;
    if (tid == 0) anyf = 0;
    __syncthreads();
    int loc = 0;
    for (int n = tid; n < NPTS; n += 256)
        if (pmask[b * NPTS + n] == s + 1) loc = 1;
    if (loc) anyf = 1;
    const float* ar = abuf + ((long)s * BATCH + b) * HID;
    ash[tid] = ar[tid];
    ash[tid + 256] = ar[tid + 256];
    __syncthreads();
    const float* W = Wo + (long)s * HID * HID;
    int has = anyf;
    for (int n = tid; n < HID; n += 256) {
        float v = 0.f;
        if (has) {
            v = bo[s * HID + n];
            #pragma unroll 4
            for (int k = 0; k < HID; k++) v += ash[k] * W[(long)k * HID + n];
        }
        out[(long)(1 + s) * (BATCH * HID) + b * HID + n] =
            bout[(((long)(s + 1) * BATCH) + b) * HID + n] + v;
    }
}

// ---------------- classifier + output copies ----------------
__global__ void k_cls(const float* __restrict__ bout,
                      const float* __restrict__ W1, const float* __restrict__ b1,
                      const float* __restrict__ W2, const float* __restrict__ b2,
                      const float* __restrict__ W3, const float* __restrict__ b3,
                      float* __restrict__ out)
{
    int b = blockIdx.x, tid = threadIdx.x;  // 128 threads
    __shared__ float tg[HID];
    __shared__ float h1[128];
    __shared__ float h2[16];
    for (int k = tid; k < HID; k += 128) tg[k] = bout[(long)b * HID + k];
    __syncthreads();
    // copy text_general and cls_feat
    for (int k = tid; k < HID; k += 128) {
        out[(long)b * HID + k] = tg[k];
        out[5L * BATCH * HID + BATCH * 3 + (long)b * HID + k] = tg[k];
    }
    float s1 = b1[tid];
    #pragma unroll 4
    for (int k = 0; k < HID; k++) s1 += tg[k] * W1[k * 128 + tid];
    h1[tid] = fmaxf(s1, 0.f);
    __syncthreads();
    if (tid < 16) {
        float s2 = b2[tid];
        #pragma unroll
        for (int k = 0; k < 128; k++) s2 += h1[k] * W2[k * 16 + tid];
        h2[tid] = fmaxf(s2, 0.f);
    }
    __syncthreads();
    if (tid < 3) {
        float s3 = b3[tid];
        #pragma unroll
        for (int k = 0; k < 16; k++) s3 += h2[k] * W3[k * 3 + tid];
        out[5L * BATCH * HID + b * 3 + tid] = s3;
    }
}

// ---------------- launch ----------------
extern "C" void kernel_launch(void* const* d_in, const int* in_sizes, int n_in,
                              void* d_out, int out_size)
{
    (void)in_sizes; (void)n_in; (void)out_size;
    const float* tfeat[5];
    for (int i = 0; i < 5; i++) tfeat[i] = (const float*)d_in[i];
    const int*   text_length = (const int*)d_in[5];
    const float* radar       = (const float*)d_in[6];
    const int*   pmask       = (const int*)d_in[7];
    const float* blk_W1  = (const float*)d_in[8];
    const float* blk_b1  = (const float*)d_in[9];
    const float* blk_W2  = (const float*)d_in[10];
    const float* blk_b2  = (const float*)d_in[11];
    const float* lstm_Wih = (const float*)d_in[12];
    const float* lstm_Whh = (const float*)d_in[13];
    const float* lstm_bih = (const float*)d_in[14];
    const float* lstm_bhh = (const float*)d_in[15];
    const float* blk_lin_W = (const float*)d_in[16];
    const float* blk_lin_b = (const float*)d_in[17];
    const float* att_Wq = (const float*)d_in[18];
    const float* att_bq = (const float*)d_in[19];
    const float* att_Wk = (const float*)d_in[20];
    const float* att_bk = (const float*)d_in[21];
    const float* att_Wv = (const float*)d_in[22];
    const float* att_bv = (const float*)d_in[23];
    const float* att_Wo = (const float*)d_in[24];
    const float* att_bo = (const float*)d_in[25];
    const float* cls_W1 = (const float*)d_in[26];
    const float* cls_b1 = (const float*)d_in[27];
    const float* cls_W2 = (const float*)d_in[28];
    const float* cls_b2 = (const float*)d_in[29];
    const float* cls_W3 = (const float*)d_in[30];
    const float* cls_b3 = (const float*)d_in[31];
    float* out = (float*)d_out;

    float *g_mid, *g_h, *g_G, *g_h0, *g_h1, *g_hs, *g_cs, *g_bo, *g_k, *g_v, *g_q, *g_a;
    cudaGetSymbolAddress((void**)&g_mid, d_mid);
    cudaGetSymbolAddress((void**)&g_h,   d_hmlp);
    cudaGetSymbolAddress((void**)&g_G,   d_G);
    cudaGetSymbolAddress((void**)&g_h0,  d_h0seq);
    cudaGetSymbolAddress((void**)&g_h1,  d_h1seq);
    cudaGetSymbolAddress((void**)&g_hs,  d_hst);
    cudaGetSymbolAddress((void**)&g_cs,  d_cst);
    cudaGetSymbolAddress((void**)&g_bo,  d_bout);
    cudaGetSymbolAddress((void**)&g_k,   d_kbuf);
    cudaGetSymbolAddress((void**)&g_v,   d_vbuf);
    cudaGetSymbolAddress((void**)&g_q,   d_qbuf);
    cudaGetSymbolAddress((void**)&g_a,   d_abuf);

    const long HSZ = (long)ROWS * HID;        // 4096*512
    const long GSZ = (long)ROWS * FH;         // 4096*2048
    const int  STATE = NBLK * BATCH * HID;    // 81920

    // 1) pre-MLP: leaky_relu(x@W1+b1) then @W2+b2
    for (int i = 0; i < 5; i++)
        k_gemm<<<dim3(8, 64, 1), 256>>>(tfeat[i], blk_W1 + (long)i * EMB * HID,
                                        blk_b1 + i * HID, nullptr,
                                        g_mid + (long)i * HSZ,
                                        ROWS, HID, EMB, 0, 0, 0, 0, 1);
    k_gemm<<<dim3(8, 64, 5), 256>>>(g_mid, blk_W2, blk_b2, nullptr, g_h,
                                    ROWS, HID, HID, HSZ, (long)HID * HID, HID, HSZ, 0);

    // 2) layer-0 input projections for all t
    k_gemm<<<dim3(32, 64, 5), 256>>>(g_h, lstm_Wih, lstm_bih, lstm_bhh, g_G,
                                     ROWS, FH, HID, HSZ, (long)2 * HID * FH, (long)2 * FH, GSZ, 0);
    k_zero<<<(2 * STATE + 1023) / 1024, 1024>>>(g_hs, 2 * STATE);
    k_zero<<<(STATE + 1023) / 1024, 1024>>>(g_cs, STATE);
    for (int t = 0; t < SEQL; t++)
        k_step<<<dim3(32, 5), 256>>>(lstm_Whh, g_G,
                                     g_hs + (t & 1) * STATE, g_hs + ((t + 1) & 1) * STATE,
                                     g_cs, g_h0, t);

    // 3) layer-1 input projections from h0 sequence
    k_gemm<<<dim3(32, 64, 5), 256>>>(g_h0, lstm_Wih + (long)HID * FH,
                                     lstm_bih + FH, lstm_bhh + FH, g_G,
                                     ROWS, FH, HID, HSZ, (long)2 * HID * FH, (long)2 * FH, GSZ, 0);
    k_zero<<<(2 * STATE + 1023) / 1024, 1024>>>(g_hs, 2 * STATE);
    k_zero<<<(STATE + 1023) / 1024, 1024>>>(g_cs, STATE);
    for (int t = 0; t < SEQL; t++)
        k_step<<<dim3(32, 5), 256>>>(lstm_Whh + (long)HID * FH, g_G,
                                     g_hs + (t & 1) * STATE, g_hs + ((t + 1) & 1) * STATE,
                                     g_cs, g_h1, t);

    // 4) gather last + linear
    k_blkout<<<dim3(5, 32), 256>>>(g_h1, text_length, blk_lin_W, blk_lin_b, g_bo);

    // 5) K/V projections (A shared across segs: strideA = 0)
    k_gemm<<<dim3(8, 512, 4), 256>>>(radar, att_Wk, att_bk, nullptr, g_k,
                                     BATCH * NPTS, HID, PDIM, 0, (long)PDIM * HID, HID,
                                     (long)BATCH * NPTS * HID, 0);
    k_gemm<<<dim3(8, 512, 4), 256>>>(radar, att_Wv, att_bv, nullptr, g_v,
                                     BATCH * NPTS, HID, PDIM, 0, (long)PDIM * HID, HID,
                                     (long)BATCH * NPTS * HID, 0);

    // 6) q projection, attention, seg output
    k_qproj<<<dim3(4, 32), 256>>>(g_bo, att_Wq, att_bq, g_q);
    k_attn<<<dim3(NHEAD, BATCH, NSEG), 256>>>(g_q, g_k, g_v, pmask, g_a);
    k_segfinal<<<dim3(4, 32), 256>>>(g_a, att_Wo, att_bo, g_bo, pmask, out);

    // 7) classifier + copies of text_general / cls_feat
    k_cls<<<32, 128>>>(g_bo, cls_W1, cls_b1, cls_W2, cls_b2, cls_W3, cls_b3, out);
}